// round 11
// baseline (speedup 1.0000x reference)
#include <cuda_runtime.h>
#include <cstdint>

// Problem constants
constexpr int B = 8;
constexpr int S = 4096;
constexpr int D = 2048;
constexpr int E = 64;

// Reduction tiling (SCHUNKS=128 measured fastest for kernel1: grid=2048)
constexpr int SCHUNKS = 128;
constexpr int SPC     = S / SCHUNKS;    // 32 rows per chunk
constexpr int DTILES  = 2;              // 2048 d -> 2 tiles of 1024 (256 thr * float4)
constexpr int THR1    = 256;

// Tail kernel layout
constexpr int FOLD_BLOCKS = 32;         // blocks 0..31: fold partials
constexpr int TAIL_BLOCKS = FOLD_BLOCKS + E;  // + 64 expert blocks = 96 (< 148 SMs: all resident)

// Static scratch (allocation-free rule)
__device__ float g_partial[(size_t)SCHUNKS * B * D];  // 8 MB
__device__ float g_mean[B * D];                       // 64 KB
__device__ float g_logits[B * E];                     // 2 KB
__device__ int   g_c1;                                // fold-done counter (zero-init, reset at end)
__device__ int   g_c2;                                // gemv-done counter

// ---------------------------------------------------------------------------
// Kernel 1: partial mean-pool sums. Each block: one (s-chunk, b, d-tile).
// Coalesced float4 loads; deterministic (no atomics). Grid = 2048 blocks.
// ---------------------------------------------------------------------------
__global__ __launch_bounds__(THR1) void partial_sum_kernel(const float* __restrict__ x) {
    int bid   = blockIdx.x;
    int chunk = bid / (B * DTILES);
    int rem   = bid % (B * DTILES);
    int b     = rem / DTILES;
    int dt    = rem % DTILES;
    int d     = dt * (THR1 * 4) + threadIdx.x * 4;

    const float4* __restrict__ xp =
        (const float4*)(x + ((size_t)b * S + (size_t)chunk * SPC) * D + d);
    const int stride4 = D / 4;  // float4 stride between consecutive s rows

    float4 acc = make_float4(0.f, 0.f, 0.f, 0.f);
#pragma unroll 8
    for (int s = 0; s < SPC; s++) {
        float4 v = xp[(size_t)s * stride4];
        acc.x += v.x; acc.y += v.y; acc.z += v.z; acc.w += v.w;
    }
    *(float4*)(g_partial + (size_t)chunk * (B * D) + (size_t)b * D + d) = acc;
}

// ---------------------------------------------------------------------------
// Kernel 2: fused tail. Grid = 96 blocks x 256 threads, all resident.
//   blocks [0,32):  fold 128 chunk-partials -> g_mean (float2/thread, deep MLP)
//   blocks [32,96): expert block e. Stage W[e] (8 KB) into smem DURING fold,
//                   spin on g_c1, then warp b computes dot(mean[b], W[e]).
//                   Ticket-63 block computes top-2 + softmax for all batches
//                   and resets the counters for the next graph replay.
// Sync is integer-counter based (release fence + atomic; observe + acquire
// fence) -> fully deterministic.
// Output: out[0..15] = weights[B][2], out[16..31] = (float)indices[B][2].
// ---------------------------------------------------------------------------
__global__ __launch_bounds__(256) void tail_kernel(const float* __restrict__ W,
                                                   const float* __restrict__ bias,
                                                   float* __restrict__ out) {
    int tid = threadIdx.x;
    int bid = blockIdx.x;

    if (bid < FOLD_BLOCKS) {
        // ---- fold: one float2 of the mean per thread, 128 chunk loads ----
        int idx = bid * 256 + tid;                      // 0..8191 (float2 index over B*D)
        const float* base = g_partial + (size_t)idx * 2;
        float ax = 0.f, ay = 0.f;
#pragma unroll 16
        for (int c = 0; c < SCHUNKS; c++) {
            float2 v = *(const float2*)(base + (size_t)c * (B * D));
            ax += v.x; ay += v.y;
        }
        const float inv = 1.0f / (float)S;
        float2 m = make_float2(ax * inv, ay * inv);
        *(float2*)(g_mean + (size_t)idx * 2) = m;

        __syncthreads();
        if (tid == 0) {
            __threadfence();                            // release g_mean writes
            atomicAdd(&g_c1, 1);
        }
        return;
    }

    // ---- expert block ----
    int e    = bid - FOLD_BLOCKS;                       // 0..63
    int lane = tid & 31;
    int b    = tid >> 5;                                // warp = batch, 0..7

    __shared__ float4 wsm[D / 4];                       // 8 KB: W row e
    __shared__ int    s_ticket;
    __shared__ float  s_logits[B * E];                  // for the top-2 block

    // Stage W[e] into smem — overlaps with the fold blocks' work
    {
        const float4* __restrict__ wp = (const float4*)(W + (size_t)e * D);
#pragma unroll
        for (int i = tid; i < D / 4; i += 256) wsm[i] = wp[i];
    }

    // Wait for fold completion
    if (tid == 0) {
        while (*(volatile int*)&g_c1 != FOLD_BLOCKS) __nanosleep(64);
        __threadfence();                                // acquire g_mean
    }
    __syncthreads();

    // GEMV: warp b -> dot(mean[b], W[e])
    {
        const float4* __restrict__ xp = (const float4*)(g_mean + (size_t)b * D);
        float sum = 0.f;
#pragma unroll
        for (int i = 0; i < (D / 4) / 32; i++) {        // 16 float4 per lane
            int idx   = lane + i * 32;
            float4 w4 = wsm[idx];
            float4 x4 = xp[idx];
            sum += w4.x * x4.x + w4.y * x4.y + w4.z * x4.z + w4.w * x4.w;
        }
#pragma unroll
        for (int o = 16; o > 0; o >>= 1) sum += __shfl_xor_sync(0xffffffffu, sum, o);
        if (lane == 0) g_logits[b * E + e] = sum + bias[e];
    }
    __syncthreads();

    // Ticket: last block to finish does the top-2 + softmax for all batches
    if (tid == 0) {
        __threadfence();                                // release this block's logits
        int t = atomicAdd(&g_c2, 1);
        if (t == E - 1) __threadfence();                // acquire all logits
        s_ticket = t;
    }
    __syncthreads();

    if (s_ticket == E - 1) {
        // Pull all logits into smem (64 threads, one expert-column each... simple copy)
        for (int i = tid; i < B * E; i += 256) s_logits[i] = g_logits[i];
        __syncthreads();

        if (tid < B) {
            const float* lg = s_logits + tid * E;
            float v1 = -1e30f, v2 = -1e30f;
            int   i1 = 0, i2 = 0;
#pragma unroll
            for (int k = 0; k < E; k++) {
                float v = lg[k];
                if (v > v1) { v2 = v1; i2 = i1; v1 = v; i1 = k; }
                else if (v > v2) { v2 = v; i2 = k; }
            }
            float e2 = __expf(v2 - v1);                 // stable 2-way softmax
            float denom = 1.0f + e2;
            out[tid * 2 + 0]      = 1.0f / denom;
            out[tid * 2 + 1]      = e2 / denom;
            out[16 + tid * 2 + 0] = (float)i1;
            out[16 + tid * 2 + 1] = (float)i2;
        }
        __syncthreads();
        if (tid == 0) {                                 // reset for next graph replay
            __threadfence();
            g_c1 = 0;
            g_c2 = 0;
        }
    }
}

extern "C" void kernel_launch(void* const* d_in, const int* in_sizes, int n_in,
                              void* d_out, int out_size) {
    const float* x    = (const float*)d_in[0];  // [B, S, D] fp32
    const float* W    = (const float*)d_in[1];  // [E, D]   fp32
    const float* bias = (const float*)d_in[2];  // [E]      fp32
    float* out        = (float*)d_out;          // 32 floats: weights then indices

    partial_sum_kernel<<<SCHUNKS * B * DTILES, THR1>>>(x);
    tail_kernel<<<TAIL_BLOCKS, 256>>>(W, bias, out);
}

// round 12
// speedup vs baseline: 1.1028x; 1.1028x over previous
#include <cuda_runtime.h>
#include <cstdint>

// Problem constants
constexpr int B = 8;
constexpr int S = 4096;
constexpr int D = 2048;
constexpr int E = 64;

// Single fused kernel layout
constexpr int DTILES = 2;               // 2048 d -> 2 tiles of 1024 floats (256 thr * float4)
constexpr int PAIRS  = B * DTILES;      // 16 (b, dtile) pairs
constexpr int SUBS   = 32;              // compute blocks per pair
constexpr int GRID   = PAIRS * SUBS;    // 512 blocks: all co-resident (4/SM * 148 = 592)
constexpr int RPB    = S / SUBS;        // 128 rows summed per block
constexpr int THR    = 256;

constexpr int FOLD_BLOCKS   = 32;       // blocks [0,32): fold phase
constexpr int EXPERT_BLOCKS = E;        // blocks [32,96): one expert each

// Static scratch (allocation-free rule)
__device__ float g_partial[GRID * 1024];   // 2 MB, one 1024-float partial per block
__device__ float g_mean[B * D];            // 64 KB
__device__ float g_logits[B * E];          // 2 KB
__device__ int   g_c0;                     // phase-1 arrivals (zero-init; reset at end)
__device__ int   g_c1;                     // fold arrivals
__device__ int   g_c2;                     // gemv ticket

// ---------------------------------------------------------------------------
// ONE persistent kernel:
//  Phase 1 (all 512 blocks): partial mean-pool sums, coalesced float4 loads,
//    128 rows/block -> g_partial[bid].  Release-fence + count on g_c0.
//  Phase 2 (blocks 0..31): spin g_c0==512, fold 32 partials per (b,d)
//    position -> g_mean (float2/thread, fully unrolled).  Count on g_c1.
//  Phase 3 (blocks 32..95 = expert e): W[e] row staged to smem DURING
//    phase 1/2, spin g_c1==32, warp b computes dot(mean[b], W[e]) -> logits.
//  Phase 4: ticket-last expert block does top-2 + 2-way softmax per batch
//    (strict > = lowest-index tie-break, matches jax.lax.top_k) and resets
//    the counters so graph replays start clean.
//  Blocks 96..511 exit after phase 1.
// All cross-block sync is monotonic-counter based with threadfence
// release/acquire; every float reduction has a fixed order -> deterministic.
// Output: out[0..15] = weights[B][2], out[16..31] = (float)indices[B][2].
// ---------------------------------------------------------------------------
__global__ __launch_bounds__(THR, 4) void fused_kernel(const float* __restrict__ x,
                                                       const float* __restrict__ W,
                                                       const float* __restrict__ bias,
                                                       float* __restrict__ out) {
    int bid  = blockIdx.x;
    int tid  = threadIdx.x;
    int pair = bid / SUBS;
    int sub  = bid % SUBS;
    int b    = pair >> 1;
    int dt   = pair & 1;

    __shared__ float4 wsm[D / 4];          // 8 KB (used by expert blocks)
    __shared__ float  s_logits[B * E];     // 2 KB (used by the ticket block)
    __shared__ int    s_ticket;

    // ---------------- Phase 1: partial sums (every block) ----------------
    {
        const float4* __restrict__ xp =
            (const float4*)(x + ((size_t)b * S + (size_t)sub * RPB) * D + dt * 1024 + tid * 4);
        float4 acc = make_float4(0.f, 0.f, 0.f, 0.f);
#pragma unroll 16
        for (int s = 0; s < RPB; s++) {
            float4 v = xp[(size_t)s * (D / 4)];
            acc.x += v.x; acc.y += v.y; acc.z += v.z; acc.w += v.w;
        }
        *(float4*)(g_partial + (size_t)bid * 1024 + tid * 4) = acc;
    }
    __syncthreads();
    if (tid == 0) {
        __threadfence();                    // release partial writes
        atomicAdd(&g_c0, 1);
    }

    if (bid >= FOLD_BLOCKS + EXPERT_BLOCKS) return;   // blocks 96..511 done

    if (bid < FOLD_BLOCKS) {
        // ---------------- Phase 2: fold -> g_mean ----------------
        if (tid == 0) {
            while (*(volatile int*)&g_c0 != GRID) __nanosleep(32);
            __threadfence();                // acquire all partials
        }
        __syncthreads();

        int idx = bid * THR + tid;          // float2 index over B*D: 0..8191
        int p   = idx >> 9;                 // pair (512 float2 per pair-slice)
        int j2  = idx & 511;
        const float* base = g_partial + (size_t)p * SUBS * 1024 + j2 * 2;
        float ax = 0.f, ay = 0.f;
#pragma unroll
        for (int s = 0; s < SUBS; s++) {
            float2 v = *(const float2*)(base + (size_t)s * 1024);
            ax += v.x; ay += v.y;
        }
        const float inv = 1.0f / (float)S;
        *(float2*)(g_mean + (size_t)idx * 2) = make_float2(ax * inv, ay * inv);

        __syncthreads();
        if (tid == 0) {
            __threadfence();                // release mean writes
            atomicAdd(&g_c1, 1);
        }
        return;
    }

    // ---------------- Phase 3: expert block (GEMV) ----------------
    int e    = bid - FOLD_BLOCKS;           // 0..63
    int lane = tid & 31;
    int bb   = tid >> 5;                    // warp = batch 0..7

    // Stage W[e] into smem — overlaps with fold blocks' work
    {
        const float4* __restrict__ wp = (const float4*)(W + (size_t)e * D);
#pragma unroll
        for (int i = tid; i < D / 4; i += THR) wsm[i] = wp[i];
    }

    if (tid == 0) {
        while (*(volatile int*)&g_c1 != FOLD_BLOCKS) __nanosleep(32);
        __threadfence();                    // acquire g_mean
    }
    __syncthreads();

    {
        const float4* __restrict__ xp = (const float4*)(g_mean + (size_t)bb * D);
        float sum = 0.f;
#pragma unroll
        for (int i = 0; i < (D / 4) / 32; i++) {   // 16 float4 per lane
            int idx   = lane + i * 32;
            float4 w4 = wsm[idx];
            float4 x4 = xp[idx];
            sum += w4.x * x4.x + w4.y * x4.y + w4.z * x4.z + w4.w * x4.w;
        }
#pragma unroll
        for (int o = 16; o > 0; o >>= 1) sum += __shfl_xor_sync(0xffffffffu, sum, o);
        if (lane == 0) g_logits[bb * E + e] = sum + bias[e];
    }
    __syncthreads();

    // ---------------- Phase 4: ticket -> top-2 + softmax ----------------
    if (tid == 0) {
        __threadfence();                    // release this block's logits
        int t = atomicAdd(&g_c2, 1);
        if (t == EXPERT_BLOCKS - 1) __threadfence();   // acquire all logits
        s_ticket = t;
    }
    __syncthreads();

    if (s_ticket == EXPERT_BLOCKS - 1) {
        for (int i = tid; i < B * E; i += THR) s_logits[i] = g_logits[i];
        __syncthreads();

        if (tid < B) {
            const float* lg = s_logits + tid * E;
            float v1 = -1e30f, v2 = -1e30f;
            int   i1 = 0, i2 = 0;
#pragma unroll
            for (int k = 0; k < E; k++) {
                float v = lg[k];
                if (v > v1) { v2 = v1; i2 = i1; v1 = v; i1 = k; }
                else if (v > v2) { v2 = v; i2 = k; }
            }
            float e2 = __expf(v2 - v1);     // stable 2-way softmax
            float denom = 1.0f + e2;
            out[tid * 2 + 0]      = 1.0f / denom;
            out[tid * 2 + 1]      = e2 / denom;
            out[16 + tid * 2 + 0] = (float)i1;
            out[16 + tid * 2 + 1] = (float)i2;
        }
        __syncthreads();
        if (tid == 0) {                     // reset for next graph replay;
            __threadfence();                // all counter consumers have passed by now
            g_c0 = 0;
            g_c1 = 0;
            g_c2 = 0;
        }
    }
}

extern "C" void kernel_launch(void* const* d_in, const int* in_sizes, int n_in,
                              void* d_out, int out_size) {
    const float* x    = (const float*)d_in[0];  // [B, S, D] fp32
    const float* W    = (const float*)d_in[1];  // [E, D]   fp32
    const float* bias = (const float*)d_in[2];  // [E]      fp32
    float* out        = (float*)d_out;          // 32 floats: weights then indices

    fused_kernel<<<GRID, THR>>>(x, W, bias, out);
}

// round 13
// speedup vs baseline: 1.1793x; 1.0693x over previous
#include <cuda_runtime.h>
#include <cstdint>

// Problem constants
constexpr int B = 8;
constexpr int S = 4096;
constexpr int D = 2048;
constexpr int E = 64;

// Single fused kernel layout — grid exactly fills 148 SMs * 4 blocks
constexpr int DTILES = 2;               // 2048 d -> 2 tiles of 1024 floats (256 thr * float4)
constexpr int PAIRS  = B * DTILES;      // 16 (b, dtile) pairs
constexpr int SUBS   = 37;              // compute blocks per pair
constexpr int GRID   = PAIRS * SUBS;    // 592 = 148 * 4: perfectly balanced, all co-resident
constexpr int THR    = 256;
// rows per sub: subs 0..25 get 111 rows, subs 26..36 get 110  (26*111 + 11*110 = 4096)

constexpr int FOLD_BLOCKS   = 32;       // blocks [0,32): fold phase
constexpr int EXPERT_BLOCKS = E;        // blocks [32,96): one expert each

// Static scratch (allocation-free rule)
__device__ float g_partial[GRID * 1024];   // 2.3 MB, one 1024-float partial per block
__device__ float g_mean[B * D];            // 64 KB
__device__ float g_logits[B * E];          // 2 KB
__device__ int   g_c0;                     // phase-1 arrivals (zero-init; reset at end)
__device__ int   g_c1;                     // fold arrivals
__device__ int   g_c2;                     // gemv ticket

// ---------------------------------------------------------------------------
// ONE persistent kernel (all cross-block sync = monotonic counters with
// threadfence release/acquire; every float reduction has a fixed order ->
// deterministic across graph replays):
//  Phase 1 (all 592 blocks): partial mean-pool sums, coalesced float4
//    __ldcs loads (read-once stream, evict-first), ~110 rows/block.
//  Phase 2 (blocks 0..31): spin g_c0==592, fold 37 partials per (pair,d)
//    position -> g_mean.
//  Phase 3 (blocks 32..95 = expert e): W[e] staged to smem during earlier
//    phases, spin g_c1==32, warp b computes dot(mean[b], W[e]) -> logits.
//  Phase 4: ticket-last expert block: top-2 (strict > = lowest-index
//    tie-break, matches jax.lax.top_k) + 2-way softmax, counter reset.
//  Blocks 96..511 exit after phase 1.
// Output: out[0..15] = weights[B][2], out[16..31] = (float)indices[B][2].
// ---------------------------------------------------------------------------
__global__ __launch_bounds__(THR, 4) void fused_kernel(const float* __restrict__ x,
                                                       const float* __restrict__ W,
                                                       const float* __restrict__ bias,
                                                       float* __restrict__ out) {
    int bid  = blockIdx.x;
    int tid  = threadIdx.x;
    int pair = bid & 15;                   // 0..15
    int sub  = bid >> 4;                   // 0..36
    int b    = pair >> 1;
    int dt   = pair & 1;

    __shared__ float4 wsm[D / 4];          // 8 KB (used by expert blocks)
    __shared__ float  s_logits[B * E];     // 2 KB (used by the ticket block)
    __shared__ int    s_ticket;

    // ---------------- Phase 1: partial sums (every block) ----------------
    {
        int row0  = sub * 110 + (sub < 26 ? sub : 26);
        int nrows = 110 + (sub < 26 ? 1 : 0);
        const float4* __restrict__ xp =
            (const float4*)(x + ((size_t)b * S + (size_t)row0) * D + dt * 1024 + tid * 4);
        float4 acc = make_float4(0.f, 0.f, 0.f, 0.f);
#pragma unroll 11
        for (int s = 0; s < nrows; s++) {
            float4 v = __ldcs(xp + (size_t)s * (D / 4));
            acc.x += v.x; acc.y += v.y; acc.z += v.z; acc.w += v.w;
        }
        *(float4*)(g_partial + (size_t)bid * 1024 + tid * 4) = acc;
    }
    __syncthreads();
    if (tid == 0) {
        __threadfence();                    // release partial writes
        atomicAdd(&g_c0, 1);
    }

    if (bid >= FOLD_BLOCKS + EXPERT_BLOCKS) return;   // blocks 96..591 done

    if (bid < FOLD_BLOCKS) {
        // ---------------- Phase 2: fold -> g_mean ----------------
        if (tid == 0) {
            while (*(volatile int*)&g_c0 != GRID) __nanosleep(32);
            __threadfence();                // acquire all partials
        }
        __syncthreads();

        int idx = bid * THR + tid;          // float2 index over B*D: 0..8191
        int p   = idx >> 9;                 // pair owning this position
        int j2  = idx & 511;                // float2 within the 1024-float slice
        const float* base = g_partial + (size_t)p * 1024 + j2 * 2;
        float ax = 0.f, ay = 0.f;
#pragma unroll
        for (int s = 0; s < SUBS; s++) {    // partial (pair, s) lives at bid = s*16 + p
            float2 v = *(const float2*)(base + (size_t)s * (PAIRS * 1024));
            ax += v.x; ay += v.y;
        }
        const float inv = 1.0f / (float)S;
        int bb = p >> 1, dd = p & 1;
        *(float2*)(g_mean + (size_t)bb * D + dd * 1024 + j2 * 2) = make_float2(ax * inv, ay * inv);

        __syncthreads();
        if (tid == 0) {
            __threadfence();                // release mean writes
            atomicAdd(&g_c1, 1);
        }
        return;
    }

    // ---------------- Phase 3: expert block (GEMV) ----------------
    int e    = bid - FOLD_BLOCKS;           // 0..63
    int lane = tid & 31;
    int bb   = tid >> 5;                    // warp = batch 0..7

    // Stage W[e] into smem — overlaps with fold blocks' work
    {
        const float4* __restrict__ wp = (const float4*)(W + (size_t)e * D);
#pragma unroll
        for (int i = tid; i < D / 4; i += THR) wsm[i] = wp[i];
    }

    if (tid == 0) {
        while (*(volatile int*)&g_c1 != FOLD_BLOCKS) __nanosleep(32);
        __threadfence();                    // acquire g_mean
    }
    __syncthreads();

    {
        const float4* __restrict__ xp = (const float4*)(g_mean + (size_t)bb * D);
        float sum = 0.f;
#pragma unroll
        for (int i = 0; i < (D / 4) / 32; i++) {   // 16 float4 per lane
            int idx   = lane + i * 32;
            float4 w4 = wsm[idx];
            float4 x4 = xp[idx];
            sum += w4.x * x4.x + w4.y * x4.y + w4.z * x4.z + w4.w * x4.w;
        }
#pragma unroll
        for (int o = 16; o > 0; o >>= 1) sum += __shfl_xor_sync(0xffffffffu, sum, o);
        if (lane == 0) g_logits[bb * E + e] = sum + bias[e];
    }
    __syncthreads();

    // ---------------- Phase 4: ticket -> top-2 + softmax ----------------
    if (tid == 0) {
        __threadfence();                    // release this block's logits
        int t = atomicAdd(&g_c2, 1);
        if (t == EXPERT_BLOCKS - 1) __threadfence();   // acquire all logits
        s_ticket = t;
    }
    __syncthreads();

    if (s_ticket == EXPERT_BLOCKS - 1) {
        for (int i = tid; i < B * E; i += THR) s_logits[i] = g_logits[i];
        __syncthreads();

        if (tid < B) {
            const float* lg = s_logits + tid * E;
            float v1 = -1e30f, v2 = -1e30f;
            int   i1 = 0, i2 = 0;
#pragma unroll
            for (int k = 0; k < E; k++) {
                float v = lg[k];
                if (v > v1) { v2 = v1; i2 = i1; v1 = v; i1 = k; }
                else if (v > v2) { v2 = v; i2 = k; }
            }
            float e2 = __expf(v2 - v1);     // stable 2-way softmax
            float denom = 1.0f + e2;
            out[tid * 2 + 0]      = 1.0f / denom;
            out[tid * 2 + 1]      = e2 / denom;
            out[16 + tid * 2 + 0] = (float)i1;
            out[16 + tid * 2 + 1] = (float)i2;
        }
        __syncthreads();
        if (tid == 0) {                     // reset for next graph replay;
            __threadfence();                // all counter consumers have passed by now
            g_c0 = 0;
            g_c1 = 0;
            g_c2 = 0;
        }
    }
}

extern "C" void kernel_launch(void* const* d_in, const int* in_sizes, int n_in,
                              void* d_out, int out_size) {
    const float* x    = (const float*)d_in[0];  // [B, S, D] fp32
    const float* W    = (const float*)d_in[1];  // [E, D]   fp32
    const float* bias = (const float*)d_in[2];  // [E]      fp32
    float* out        = (float*)d_out;          // 32 floats: weights then indices

    fused_kernel<<<GRID, THR>>>(x, W, bias, out);
}